// round 6
// baseline (speedup 1.0000x reference)
#include <cuda_runtime.h>
#include <cuda_fp16.h>
#include <cstdint>

#define NATOMS 200000
#define NBONDS 400000
#define NMOLS  10000
#define AFD    133
#define BFD    13
#define HID    300
#define NTASKS 12
#define SP     320          // padded feature-row stride (floats); pad cols stay 0 forever
#define NQ     75           // float4 chunks per real row (300/4)

#define KP_H0  160
#define KP_MSG 304
#define KP_AH  448
#define KP_RO  304
#define WN     320          // padded N for weights

// ---------------- device scratch ----------------
__device__ __align__(128) float g_h0[(size_t)NBONDS * SP];
__device__ __align__(128) float g_hA[(size_t)NBONDS * SP];
__device__ __align__(128) float g_hB[(size_t)NBONDS * SP];
__device__ __align__(128) float g_amsg[(size_t)NATOMS * SP];
__device__ __align__(128) float g_ah[(size_t)NATOMS * SP];
__device__ __align__(128) float g_mol[(size_t)NMOLS * SP];
__device__ __align__(128) float g_ro[(size_t)NMOLS * SP];
__device__ int g_tgt[NBONDS];
__device__ int g_cnt[NATOMS];
__device__ int g_off[NATOMS + 1];
__device__ int g_cur[NATOMS];
__device__ int g_idx[NBONDS];
__device__ int g_mstart[NMOLS + 1];
// half-precision transposed weights: WT[k][n], zero-padded
__device__ __align__(128) __half g_WiT[KP_H0  * WN];
__device__ __align__(128) __half g_WhT[KP_MSG * WN];
__device__ __align__(128) __half g_WoT[KP_AH  * WN];
__device__ __align__(128) __half g_Wr1T[KP_RO * WN];

__device__ __forceinline__ float* h_buf(int s) {
    return s == 0 ? g_h0 : (s == 1 ? g_hA : g_hB);
}
__device__ __forceinline__ uint32_t smem_u32(const void* p) {
    return (uint32_t)__cvta_generic_to_shared(p);
}
__device__ __forceinline__ uint32_t pack2(float a, float b) {
    __half2 h = __floats2half2_rn(a, b);
    return *reinterpret_cast<uint32_t*>(&h);
}

#define LDSM_X4(r0, r1, r2, r3, a) \
    asm volatile("ldmatrix.sync.aligned.m8n8.x4.shared.b16 {%0,%1,%2,%3}, [%4];" \
                 : "=r"(r0), "=r"(r1), "=r"(r2), "=r"(r3) : "r"(a))
#define LDSM_X4_T(r0, r1, r2, r3, a) \
    asm volatile("ldmatrix.sync.aligned.m8n8.x4.trans.shared.b16 {%0,%1,%2,%3}, [%4];" \
                 : "=r"(r0), "=r"(r1), "=r"(r2), "=r"(r3) : "r"(a))
#define MMA_F16(ac, a0, a1, a2, a3, b0, b1) \
    asm volatile("mma.sync.aligned.m16n8k16.row.col.f32.f16.f16.f32 " \
                 "{%0,%1,%2,%3}, {%4,%5,%6,%7}, {%8,%9}, {%0,%1,%2,%3};" \
                 : "+f"((ac)[0]), "+f"((ac)[1]), "+f"((ac)[2]), "+f"((ac)[3]) \
                 : "r"(a0), "r"(a1), "r"(a2), "r"(a3), "r"(b0), "r"(b1))

// ---------------- prep kernels ----------------
__global__ void transpose_k(const float* __restrict__ W, int Kreal, int Kpad, int sel) {
    __half* WT = sel == 0 ? g_WiT : sel == 1 ? g_WhT : sel == 2 ? g_WoT : g_Wr1T;
    int idx = blockIdx.x * blockDim.x + threadIdx.x;
    if (idx < Kpad * WN) {
        int k = idx / WN;
        int n = idx - k * WN;
        float v = (k < Kreal && n < HID) ? W[(size_t)n * Kreal + k] : 0.f;
        WT[idx] = __float2half_rn(v);
    }
}

__global__ void zerocnt_k() {
    int i = blockIdx.x * blockDim.x + threadIdx.x;
    if (i < NATOMS) g_cnt[i] = 0;
}
__global__ void tgt_hist_k(const int* __restrict__ b2a, const int* __restrict__ b2revb) {
    int i = blockIdx.x * blockDim.x + threadIdx.x;
    if (i < NBONDS) {
        int t = b2a[b2revb[i]];
        g_tgt[i] = t;
        atomicAdd(&g_cnt[t], 1);
    }
}
__global__ void scan_k() {
    __shared__ int sh[1024];
    const int per = (NATOMS + 1023) / 1024;
    int t = threadIdx.x;
    int s0 = t * per, e0 = min(s0 + per, NATOMS);
    int sum = 0;
    for (int i = s0; i < e0; i++) sum += g_cnt[i];
    sh[t] = sum;
    __syncthreads();
    for (int off = 1; off < 1024; off <<= 1) {
        int v = (t >= off) ? sh[t - off] : 0;
        __syncthreads();
        sh[t] += v;
        __syncthreads();
    }
    int run = (t == 0) ? 0 : sh[t - 1];
    for (int i = s0; i < e0; i++) {
        int c = g_cnt[i];
        g_off[i] = run;
        g_cur[i] = run;
        run += c;
    }
    if (t == 1023) g_off[NATOMS] = NBONDS;
}
__global__ void fill_k() {
    int b = blockIdx.x * blockDim.x + threadIdx.x;
    if (b < NBONDS) {
        int p = atomicAdd(&g_cur[g_tgt[b]], 1);
        g_idx[p] = b;
    }
}
__global__ void mstart_k(const int* __restrict__ mol_ids) {
    int a = blockIdx.x * blockDim.x + threadIdx.x;
    if (a < NATOMS) {
        int id = mol_ids[a];
        int prev = (a == 0) ? -1 : mol_ids[a - 1];
        for (int m = prev + 1; m <= id; m++) g_mstart[m] = a;
        if (a == NATOMS - 1)
            for (int m = id + 1; m <= NMOLS; m++) g_mstart[m] = NATOMS;
    }
}

__global__ void agg_k(int srcSel) {
    int t = blockIdx.x * blockDim.x + threadIdx.x;
    if (t >= NATOMS * NQ) return;
    int a = t / NQ;
    int q = t - a * NQ;
    int s = g_off[a], e = g_off[a + 1];
    const float* h = h_buf(srcSel);
    float4 acc = make_float4(0.f, 0.f, 0.f, 0.f);
    for (int i = s; i < e; i++) {
        int b = g_idx[i];
        float4 v = *(const float4*)(h + (size_t)b * SP + q * 4);
        acc.x += v.x; acc.y += v.y; acc.z += v.z; acc.w += v.w;
    }
    *(float4*)(g_amsg + (size_t)a * SP + q * 4) = acc;
}

__global__ void poolagg_k() {
    int t = blockIdx.x * blockDim.x + threadIdx.x;
    if (t >= NMOLS * NQ) return;
    int m = t / NQ;
    int q = t - m * NQ;
    int s = g_mstart[m], e = g_mstart[m + 1];
    float4 acc = make_float4(0.f, 0.f, 0.f, 0.f);
    for (int a = s; a < e; a++) {
        float4 v = *(const float4*)(g_ah + (size_t)a * SP + q * 4);
        acc.x += v.x; acc.y += v.y; acc.z += v.z; acc.w += v.w;
    }
    *(float4*)(g_mol + (size_t)m * SP + q * 4) = acc;
}

__global__ void logits_k(const float* __restrict__ Wr2, const float* __restrict__ br2,
                         float* __restrict__ out) {
    int idx = blockIdx.x * blockDim.x + threadIdx.x;
    if (idx < NMOLS * NTASKS) {
        int m = idx / NTASKS;
        int t = idx - m * NTASKS;
        const float* x = &g_ro[(size_t)m * SP];
        const float* w = &Wr2[t * HID];
        float s = br2[t];
#pragma unroll 4
        for (int k = 0; k < HID; k++) s += x[k] * w[k];
        out[idx] = s;
    }
}

// ---------------- fused gather-GEMM: fp16 mma.sync + ldmatrix ----------------
// C[M x 300] = relu( A_gathered[M x Kpad] @ WT + bias + optional h0 )
// BM=128, BN=64, BK=16 (halves); 8 warps = 4M x 2N; warp tile 32x32.
#define ASTRH 24    // A row stride in halves (48 B: 12-word stride, ldmatrix conflict-free)
#define BSTRH 72    // B row stride in halves (144 B: 36-word stride, conflict-free)

enum { MODE_H0 = 0, MODE_MSG = 1, MODE_AH = 2, MODE_RO = 3 };

template <int MODE>
__global__ __launch_bounds__(256, 2)
void gemm_k(int M, int srcSel, int dstSel,
            const float* __restrict__ fa, const float* __restrict__ fb,
            const int* __restrict__ b2a, const int* __restrict__ b2revb,
            const float* __restrict__ bias) {
    __shared__ __half As[2][128 * ASTRH];
    __shared__ __half Bs[2][16 * BSTRH];

    const int tid  = threadIdx.x;
    const int lane = tid & 31;
    const int wid  = tid >> 5;
    const int g    = lane >> 2;
    const int tig  = lane & 3;
    const int wm   = wid & 3;
    const int wn   = wid >> 2;
    const int mrow = wm * 32;
    const int ncol = wn * 32;
    const int n0   = blockIdx.x * 64;
    const int m0   = blockIdx.y * 128;

    const int Kpad = (MODE == MODE_H0) ? KP_H0 : (MODE == MODE_AH) ? KP_AH
                   : (MODE == MODE_MSG) ? KP_MSG : KP_RO;
    const __half* WT = (MODE == MODE_H0)  ? g_WiT
                     : (MODE == MODE_MSG) ? g_WhT
                     : (MODE == MODE_AH)  ? g_WoT
                                          : g_Wr1T;
    float* C = (MODE == MODE_H0)  ? g_h0
             : (MODE == MODE_MSG) ? h_buf(dstSel)
             : (MODE == MODE_AH)  ? g_ah
                                  : g_ro;

    // per-thread A row (2 threads per row, 8 halves each)
    const int r     = tid >> 1;
    const int hlf   = tid & 1;
    const int gm    = m0 + r;
    const bool rok  = gm < M;
    const int gmc   = rok ? gm : 0;
    const float* arow = nullptr;
    const float* hrow = nullptr;
    int ia = 0;
    if (MODE == MODE_MSG) {
        arow = g_amsg + (size_t)b2a[gmc] * SP;
        hrow = h_buf(srcSel) + (size_t)b2revb[gmc] * SP;
    } else if (MODE == MODE_H0) {
        ia = b2a[gmc];
    } else if (MODE == MODE_RO) {
        arow = g_mol + (size_t)gmc * SP;
    }

    float acc[2][4][4];
#pragma unroll
    for (int mi = 0; mi < 2; mi++)
#pragma unroll
        for (int ni = 0; ni < 4; ni++)
#pragma unroll
            for (int c = 0; c < 4; c++) acc[mi][ni][c] = 0.f;

    float4 xa[2], xh[2];
    float  vsc[8];

    auto stage = [&](int t) {
        const int kb = t * 16 + hlf * 8;
        if (MODE == MODE_MSG) {
            xa[0] = *(const float4*)(arow + kb);
            xa[1] = *(const float4*)(arow + kb + 4);
            xh[0] = *(const float4*)(hrow + kb);
            xh[1] = *(const float4*)(hrow + kb + 4);
        } else if (MODE == MODE_RO) {
            xa[0] = *(const float4*)(arow + kb);
            xa[1] = *(const float4*)(arow + kb + 4);
        } else {
#pragma unroll
            for (int e = 0; e < 8; e++) {
                int k = kb + e;
                float x = 0.f;
                if (MODE == MODE_H0) {
                    x = (k < AFD) ? fa[(size_t)ia * AFD + k]
                      : (k < AFD + BFD) ? fb[(size_t)gmc * BFD + (k - AFD)] : 0.f;
                } else {  // MODE_AH
                    x = (k < AFD) ? fa[(size_t)gmc * AFD + k]
                      : (k < AFD + HID) ? g_amsg[(size_t)gmc * SP + (k - AFD)] : 0.f;
                }
                vsc[e] = x;
            }
        }
    };

    auto storeA = [&](int buf) {
        uint32_t u[4];
        if (MODE == MODE_MSG) {
            u[0] = pack2(xa[0].x - xh[0].x, xa[0].y - xh[0].y);
            u[1] = pack2(xa[0].z - xh[0].z, xa[0].w - xh[0].w);
            u[2] = pack2(xa[1].x - xh[1].x, xa[1].y - xh[1].y);
            u[3] = pack2(xa[1].z - xh[1].z, xa[1].w - xh[1].w);
        } else if (MODE == MODE_RO) {
            u[0] = pack2(xa[0].x, xa[0].y);
            u[1] = pack2(xa[0].z, xa[0].w);
            u[2] = pack2(xa[1].x, xa[1].y);
            u[3] = pack2(xa[1].z, xa[1].w);
        } else {
            u[0] = pack2(vsc[0], vsc[1]);
            u[1] = pack2(vsc[2], vsc[3]);
            u[2] = pack2(vsc[4], vsc[5]);
            u[3] = pack2(vsc[6], vsc[7]);
        }
        uint32_t dst = smem_u32(As[buf]) + r * (ASTRH * 2) + hlf * 16;
        asm volatile("st.shared.v4.b32 [%0], {%1,%2,%3,%4};"
                     :: "r"(dst), "r"(u[0]), "r"(u[1]), "r"(u[2]), "r"(u[3]) : "memory");
    };

    auto cpB = [&](int t, int buf) {
        if (tid < 128) {
            const int kk = tid >> 3;
            const int j  = tid & 7;
            const __half* src = WT + (size_t)(t * 16 + kk) * WN + n0 + j * 8;
            uint32_t dst = smem_u32(Bs[buf]) + kk * (BSTRH * 2) + j * 16;
            asm volatile("cp.async.ca.shared.global [%0], [%1], 16;"
                         :: "r"(dst), "l"(src));
        }
    };

    auto domma = [&](int buf) {
        const uint32_t abase = smem_u32(As[buf]);
        const uint32_t bbase = smem_u32(Bs[buf]);
        uint32_t af[2][4];
#pragma unroll
        for (int mi = 0; mi < 2; mi++) {
            uint32_t addr = abase + (mrow + mi * 16 + (lane & 15)) * (ASTRH * 2)
                          + (lane >> 4) * 16;
            LDSM_X4(af[mi][0], af[mi][1], af[mi][2], af[mi][3], addr);
        }
        uint32_t bf[4][2];
#pragma unroll
        for (int nip = 0; nip < 2; nip++) {
            uint32_t addr = bbase + (lane & 15) * (BSTRH * 2)
                          + (ncol + nip * 16 + (lane >> 4) * 8) * 2;
            LDSM_X4_T(bf[nip * 2][0], bf[nip * 2][1],
                      bf[nip * 2 + 1][0], bf[nip * 2 + 1][1], addr);
        }
#pragma unroll
        for (int mi = 0; mi < 2; mi++)
#pragma unroll
            for (int ni = 0; ni < 4; ni++)
                MMA_F16(acc[mi][ni], af[mi][0], af[mi][1], af[mi][2], af[mi][3],
                        bf[ni][0], bf[ni][1]);
    };

    const int T = Kpad / 16;

    // prologue
    stage(0);
    cpB(0, 0);
    asm volatile("cp.async.commit_group;" ::: "memory");
    storeA(0);
    asm volatile("cp.async.wait_group 0;" ::: "memory");
    __syncthreads();

    for (int t = 0; t < T; t++) {
        const int cur = t & 1;
        const int nxt = cur ^ 1;
        const bool more = (t + 1 < T);
        if (more) {
            stage(t + 1);
            cpB(t + 1, nxt);
            asm volatile("cp.async.commit_group;" ::: "memory");
        }
        domma(cur);
        __syncthreads();
        if (more) {
            storeA(nxt);
            asm volatile("cp.async.wait_group 0;" ::: "memory");
            __syncthreads();
        }
    }

    // ---- epilogue (float2 lanes; gn always even) ----
#pragma unroll
    for (int mi = 0; mi < 2; mi++) {
#pragma unroll
        for (int ni = 0; ni < 4; ni++) {
            int gn = n0 + ncol + ni * 8 + tig * 2;
            if (gn >= HID) continue;
#pragma unroll
            for (int hf = 0; hf < 2; hf++) {
                int row = m0 + mrow + mi * 16 + g + hf * 8;
                if (row >= M) continue;
                float2 v = make_float2(acc[mi][ni][hf * 2], acc[mi][ni][hf * 2 + 1]);
                if (MODE == MODE_MSG) {
                    float2 h0v = *(const float2*)(g_h0 + (size_t)row * SP + gn);
                    v.x += h0v.x; v.y += h0v.y;
                }
                if (MODE == MODE_AH || MODE == MODE_RO) {
                    float2 b2v = *(const float2*)(bias + gn);
                    v.x += b2v.x; v.y += b2v.y;
                }
                v.x = fmaxf(v.x, 0.f);
                v.y = fmaxf(v.y, 0.f);
                *(float2*)(C + (size_t)row * SP + gn) = v;
            }
        }
    }
}

static inline int cdiv(int a, int b) { return (a + b - 1) / b; }

extern "C" void kernel_launch(void* const* d_in, const int* in_sizes, int n_in,
                              void* d_out, int out_size) {
    const float* f_atoms = (const float*)d_in[0];
    const float* f_bonds = (const float*)d_in[1];
    const int*   b2a     = (const int*)d_in[2];
    const int*   b2revb  = (const int*)d_in[3];
    const int*   mol_ids = (const int*)d_in[4];
    const float* W_i     = (const float*)d_in[5];
    const float* W_h     = (const float*)d_in[6];
    const float* W_o     = (const float*)d_in[7];
    const float* b_o     = (const float*)d_in[8];
    const float* W_r1    = (const float*)d_in[9];
    const float* b_r1    = (const float*)d_in[10];
    const float* W_r2    = (const float*)d_in[11];
    const float* b_r2    = (const float*)d_in[12];
    float* out = (float*)d_out;

    // weights -> half, transposed [k][320], zero-padded
    transpose_k<<<cdiv(KP_H0  * WN, 256), 256>>>(W_i,  AFD + BFD, KP_H0,  0);
    transpose_k<<<cdiv(KP_MSG * WN, 256), 256>>>(W_h,  HID,       KP_MSG, 1);
    transpose_k<<<cdiv(KP_AH  * WN, 256), 256>>>(W_o,  AFD + HID, KP_AH,  2);
    transpose_k<<<cdiv(KP_RO  * WN, 256), 256>>>(W_r1, HID,       KP_RO,  3);

    // CSR build (bond -> target atom) + molecule ranges
    zerocnt_k<<<cdiv(NATOMS, 256), 256>>>();
    tgt_hist_k<<<cdiv(NBONDS, 256), 256>>>(b2a, b2revb);
    scan_k<<<1, 1024>>>();
    fill_k<<<cdiv(NBONDS, 256), 256>>>();
    mstart_k<<<cdiv(NATOMS, 256), 256>>>(mol_ids);

    dim3 gB(5, NBONDS / 128);        // 5 x 3125
    dim3 gA(5, cdiv(NATOMS, 128));   // 5 x 1563
    dim3 gM(5, cdiv(NMOLS, 128));    // 5 x 79

    // h0 = relu(concat(f_atoms[b2a], f_bonds) @ W_i^T)
    gemm_k<MODE_H0><<<gB, 256>>>(NBONDS, 0, 0, f_atoms, f_bonds, b2a, b2revb, nullptr);

    // 3 message-passing iterations (h0 -> hA -> hB -> hA)
    int src = 0;
    const int nxt[3] = {1, 2, 1};
    for (int d = 0; d < 3; d++) {
        agg_k<<<cdiv(NATOMS * NQ, 256), 256>>>(src);
        gemm_k<MODE_MSG><<<gB, 256>>>(NBONDS, src, nxt[d], nullptr, nullptr,
                                      b2a, b2revb, nullptr);
        src = nxt[d];
    }

    // final aggregation + atom output
    agg_k<<<cdiv(NATOMS * NQ, 256), 256>>>(src);
    gemm_k<MODE_AH><<<gA, 256>>>(NATOMS, 0, 0, f_atoms, nullptr, nullptr, nullptr, b_o);

    // per-molecule pooling (sorted mol_ids -> contiguous ranges)
    poolagg_k<<<cdiv(NMOLS * NQ, 256), 256>>>();

    // readout
    gemm_k<MODE_RO><<<gM, 256>>>(NMOLS, 0, 0, nullptr, nullptr, nullptr, nullptr, b_r1);
    logits_k<<<cdiv(NMOLS * NTASKS, 256), 256>>>(W_r2, b_r2, out);
}